// round 11
// baseline (speedup 1.0000x reference)
#include <cuda_runtime.h>
#include <cuda_fp16.h>
#include <cstdint>

// Problem constants
#define BB    64
#define CDIM  128
#define NPX   1024
#define WDIM  147584          // 128*128*9 + 128
#define WOFF  147456

// ---------------------------------------------------------------------------
// Device scratch
// w_h   : fp16 conv weights            [b][tap=9][o=128][c=128]
// cat_h : fp16 TRANSPOSED concat input [b][px=1024][c=256]
// pw_h  : fp16 proj weights            [o=128][c=256]
// g_padh: fp16 projected input         [b][y=34][x=32][c=128]  (y pads = 0)
// ---------------------------------------------------------------------------
__device__ __half w_h  [(size_t)BB * 9 * CDIM * CDIM];
__device__ __half cat_h[(size_t)BB * NPX * 256];
__device__ __half pw_h [CDIM * 256];
__device__ __half g_padh[(size_t)BB * 34 * 32 * CDIM];

// ===========================================================================
// helpers
// ===========================================================================
__device__ __forceinline__ uint32_t smem_u32(const void* p) {
    uint32_t a;
    asm("{ .reg .u64 t; cvta.to.shared.u64 t, %1; cvt.u32.u64 %0, t; }"
        : "=r"(a) : "l"(p));
    return a;
}

#define CP_ASYNC16(dst_u32, src_ptr) \
    asm volatile("cp.async.cg.shared.global [%0], [%1], 16;" \
                 :: "r"(dst_u32), "l"(src_ptr) : "memory")
#define CP_COMMIT() asm volatile("cp.async.commit_group;" ::: "memory")
#define CP_WAIT(N)  asm volatile("cp.async.wait_group %0;" :: "n"(N) : "memory")

#define LDSM_X4(r0,r1,r2,r3,addr) \
    asm volatile("ldmatrix.sync.aligned.m8n8.x4.shared.b16 {%0,%1,%2,%3}, [%4];" \
                 : "=r"(r0),"=r"(r1),"=r"(r2),"=r"(r3) : "r"(addr))

// m16n8k16 fp16 MMA, fp32 accumulate
__device__ __forceinline__ void mma_f16(float* d, const uint32_t* a,
                                        uint32_t b0, uint32_t b1) {
    asm volatile(
        "mma.sync.aligned.m16n8k16.row.col.f32.f16.f16.f32 "
        "{%0,%1,%2,%3}, {%4,%5,%6,%7}, {%8,%9}, {%0,%1,%2,%3};"
        : "+f"(d[0]), "+f"(d[1]), "+f"(d[2]), "+f"(d[3])
        : "r"(a[0]), "r"(a[1]), "r"(a[2]), "r"(a[3]), "r"(b0), "r"(b1));
}

// ===========================================================================
// Kernel 0 (prep, 3 roles by block id):
//  blocks [0,512)    : wtrans  -> w_h
//  blocks [512,1024) : cat transpose+fp16 -> cat_h[b][px][c]
//  block  1024       : pw -> pw_h
// ===========================================================================
#define PREP_SMEM (16 * 1152 * 4)        // 73728 B (wtrans role needs most)

__global__ __launch_bounds__(256) void prep_kernel(
    const float* __restrict__ qrep, const float* __restrict__ lhs,
    const float* __restrict__ rhs,  const float* __restrict__ pw)
{
    extern __shared__ float s[];
    const int blk = blockIdx.x, tid = threadIdx.x;

    if (blk < 512) {
        // ---- wtrans role: w_h[b][tap][o][c] = half(qrep[b, o*1152+c*9+tap])
        const int b = blk >> 3, obase = (blk & 7) * 16;
        const float* src = qrep + (size_t)b * WDIM + obase * 1152;
        #pragma unroll
        for (int i = 0; i < 18; i++) {
            int idx = tid + i * 256;
            *reinterpret_cast<float4*>(s + idx * 4) =
                *reinterpret_cast<const float4*>(src + idx * 4);
        }
        __syncthreads();
        #pragma unroll
        for (int i = 0; i < 18; i++) {
            int idx = tid + i * 256;
            int tap = idx >> 9, rem = idx & 511;
            int o = rem >> 5, c4 = rem & 31;
            const float* row = s + o * 1152 + tap;
            __half2 h0 = __floats2half2_rn(row[(c4*4+0)*9], row[(c4*4+1)*9]);
            __half2 h1 = __floats2half2_rn(row[(c4*4+2)*9], row[(c4*4+3)*9]);
            uint2 u;
            u.x = *reinterpret_cast<uint32_t*>(&h0);
            u.y = *reinterpret_cast<uint32_t*>(&h1);
            *reinterpret_cast<uint2*>(
                w_h + (((size_t)b * 9 + tap) * CDIM + obase + o) * CDIM + c4*4) = u;
        }
    } else if (blk < 1024) {
        // ---- cat role: cat_h[b][pxbase+px][c] = half(cat[b][c][px])
        const int b = (blk - 512) >> 3, pxbase = ((blk - 512) & 7) * 128;
        for (int cb = 0; cb < 256; cb += 64) {
            // load [64 c][128 px] fp32, stride 132 (16B-aligned rows)
            #pragma unroll
            for (int i = 0; i < 8; i++) {
                int f = tid + i * 256;
                int cc = f >> 5, p4 = f & 31;
                int c  = cb + cc;
                const float* src = (c < CDIM)
                    ? (lhs + ((size_t)b * CDIM + c) * NPX + pxbase + p4 * 4)
                    : (rhs + ((size_t)b * CDIM + (c - CDIM)) * NPX + pxbase + p4 * 4);
                *reinterpret_cast<float4*>(s + cc * 132 + p4 * 4) =
                    *reinterpret_cast<const float4*>(src);
            }
            __syncthreads();
            // write [128 px][64 c] fp16, coalesced uint2
            #pragma unroll
            for (int i = 0; i < 8; i++) {
                int f = tid + i * 256;
                int px = f >> 4, c4g = f & 15;
                __half2 h0 = __floats2half2_rn(s[(c4g*4+0)*132 + px],
                                               s[(c4g*4+1)*132 + px]);
                __half2 h1 = __floats2half2_rn(s[(c4g*4+2)*132 + px],
                                               s[(c4g*4+3)*132 + px]);
                uint2 u;
                u.x = *reinterpret_cast<uint32_t*>(&h0);
                u.y = *reinterpret_cast<uint32_t*>(&h1);
                *reinterpret_cast<uint2*>(
                    cat_h + ((size_t)b * NPX + pxbase + px) * 256 + cb + c4g*4) = u;
            }
            __syncthreads();
        }
    } else {
        // ---- pw role: pw_h = half(pw), 32768 elements
        #pragma unroll
        for (int i = 0; i < 32; i++) {
            int f = (tid + i * 256) * 4;
            float4 v = *reinterpret_cast<const float4*>(pw + f);
            __half2 h0 = __floats2half2_rn(v.x, v.y);
            __half2 h1 = __floats2half2_rn(v.z, v.w);
            uint2 u;
            u.x = *reinterpret_cast<uint32_t*>(&h0);
            u.y = *reinterpret_cast<uint32_t*>(&h1);
            *reinterpret_cast<uint2*>(pw_h + f) = u;
        }
    }
}

// ===========================================================================
// Kernel 1: projection, fp16 m16n8k16 + ldmatrix (clone of conv pipeline).
//   g_padh[b][1+y][x][o] = half( sum_c pw[o,c]*cat[b,c,(y,x)] + pb[o] )
// CTA: 128 o x 128 px, 8 warps (2o x 4px). K=256: 4 stages of k64,
// 3-ring, 1 sync/stage. A = pw_h rows, B = cat_h px-rows (both non-trans).
// ===========================================================================
#define SH 72                                    // smem row stride (halves)
#define OPH (128 * SH)                           // 9216 halves per operand
#define STGH (2 * OPH)                           // A + B per stage
#define PROJ_SMEM (3 * STGH * 2)                 // 110592 B
#define PNST 4

__global__ __launch_bounds__(256, 2) void proj_kernel(const float* __restrict__ pb)
{
    extern __shared__ __half smh[];
    const int tid = threadIdx.x, lane = tid & 31, warp = tid >> 5;
    const int g = lane >> 2, q = lane & 3;
    const int ow = warp & 1, pwv = warp >> 1;
    const int b = blockIdx.y, pxbase = blockIdx.x * 128;
    const uint32_t sbase = smem_u32(smh);

    const __half* bsrc = cat_h + ((size_t)b * NPX + pxbase) * 256;

    auto issue = [&](int s) {
        const uint32_t sa = sbase + ((s % 3) * STGH) * 2;
        const uint32_t sb = sa + OPH * 2;
        #pragma unroll
        for (int i = 0; i < 4; i++) {            // A: 128 o x 64 k halves
            int f = tid + i * 256;
            int r = f >> 3, k16 = f & 7;
            CP_ASYNC16(sa + (r * SH + k16 * 8) * 2,
                       pw_h + r * 256 + s * 64 + k16 * 8);
        }
        #pragma unroll
        for (int i = 0; i < 4; i++) {            // B: 128 px x 64 k halves
            int f = tid + i * 256;
            int r = f >> 3, k16 = f & 7;
            CP_ASYNC16(sb + (r * SH + k16 * 8) * 2,
                       bsrc + (size_t)r * 256 + s * 64 + k16 * 8);
        }
        CP_COMMIT();
    };

    const int aRow = ((lane >> 3) & 1) * 8 + (lane & 7);
    const int aK   = (lane >> 4) * 8;
    const int m    = lane >> 3;
    const int bRow = (m >> 1) * 8 + (lane & 7);
    const int bK   = (m & 1) * 8;

    float acc[4][4][4];
    #pragma unroll
    for (int mt = 0; mt < 4; mt++)
        #pragma unroll
        for (int nt = 0; nt < 4; nt++)
            #pragma unroll
            for (int k = 0; k < 4; k++) acc[mt][nt][k] = 0.f;

    issue(0); issue(1);
    for (int s = 0; s < PNST; s++) {
        if (s + 1 < PNST) CP_WAIT(1);
        else              CP_WAIT(0);
        __syncthreads();
        if (s + 2 < PNST) issue(s + 2);

        const uint32_t aBase = sbase + ((s % 3) * STGH) * 2;
        const uint32_t bBase = aBase + OPH * 2;
        #pragma unroll
        for (int j = 0; j < 4; j++) {
            uint32_t af[4][4], bf[2][4];
            #pragma unroll
            for (int mt = 0; mt < 4; mt++) {
                uint32_t addr = aBase +
                    ((ow * 64 + mt * 16 + aRow) * SH + j * 16 + aK) * 2;
                LDSM_X4(af[mt][0], af[mt][1], af[mt][2], af[mt][3], addr);
            }
            #pragma unroll
            for (int ntp = 0; ntp < 2; ntp++) {
                uint32_t addr = bBase +
                    ((pwv * 32 + ntp * 16 + bRow) * SH + j * 16 + bK) * 2;
                LDSM_X4(bf[ntp][0], bf[ntp][1], bf[ntp][2], bf[ntp][3], addr);
            }
            #pragma unroll
            for (int nt = 0; nt < 4; nt++) {
                uint32_t b0 = bf[nt >> 1][(nt & 1) * 2];
                uint32_t b1 = bf[nt >> 1][(nt & 1) * 2 + 1];
                #pragma unroll
                for (int mt = 0; mt < 4; mt++)
                    mma_f16(acc[mt][nt], af[mt], b0, b1);
            }
        }
    }
    __syncthreads();                             // smem reused as T below

    // Epilogue: +bias, transpose through smem, fp16 store to g_padh
    float* T = reinterpret_cast<float*>(smh);    // [128 px][132]
    #pragma unroll
    for (int mt = 0; mt < 4; mt++) {
        int o = ow * 64 + mt * 16 + g;
        float bl = __ldg(pb + o), bh = __ldg(pb + o + 8);
        #pragma unroll
        for (int nt = 0; nt < 4; nt++) {
            int n0 = pwv * 32 + nt * 8 + 2 * q;
            T[n0 * 132 + o]           = acc[mt][nt][0] + bl;
            T[(n0 + 1) * 132 + o]     = acc[mt][nt][1] + bl;
            T[n0 * 132 + o + 8]       = acc[mt][nt][2] + bh;
            T[(n0 + 1) * 132 + o + 8] = acc[mt][nt][3] + bh;
        }
    }
    __syncthreads();
    #pragma unroll
    for (int i = 0; i < 16; i++) {
        int idx = tid + i * 256;
        int row = idx >> 5, c4 = idx & 31;
        int px = pxbase + row, y = px >> 5, x = px & 31;
        float4 v = *reinterpret_cast<const float4*>(T + row * 132 + c4 * 4);
        __half2 h0 = __floats2half2_rn(v.x, v.y);
        __half2 h1 = __floats2half2_rn(v.z, v.w);
        uint2 u;
        u.x = *reinterpret_cast<uint32_t*>(&h0);
        u.y = *reinterpret_cast<uint32_t*>(&h1);
        *reinterpret_cast<uint2*>(
            g_padh + (((size_t)b * 34 + 1 + y) * 32 + x) * CDIM + c4 * 4) = u;
    }
}

// ===========================================================================
// Kernel 2: conv, fp16 m16n8k16, RESIDENT B window + streamed A. (as R10)
// ===========================================================================
#define CBH 136                                  // B smem (row,x) stride (halves)
#define B_RES (6 * 34 * CBH)                     // 27744 halves
#define A_STG (128 * SH)                         // 9216 halves
#define CONV_SMEM ((B_RES + 3 * A_STG) * 2)      // 110784 B
#define NSTG 18

__global__ __launch_bounds__(256, 2) void conv_kernel(
    const float* __restrict__ qrep, float* __restrict__ out)
{
    extern __shared__ __half smh[];
    const int tid = threadIdx.x, lane = tid & 31, warp = tid >> 5;
    const int g = lane >> 2, q = lane & 3;
    const int ow = warp & 1, pwv = warp >> 1;
    const int ytile = blockIdx.x, b = blockIdx.y;
    const uint32_t sbase = smem_u32(smh);

    // ---- B: zero the two x-pad column slots, then load the 6x32 window
    #pragma unroll
    for (int i = tid; i < 6 * 2 * 16; i += 256) {
        int rr = i >> 5, rem = i & 31;
        int side = rem >> 4, u = rem & 15;
        int x = side ? 33 : 0;
        *reinterpret_cast<uint4*>(smh + (rr * 34 + x) * CBH + u * 8) =
            make_uint4(0, 0, 0, 0);
    }
    {
        const __half* bsrc = g_padh + ((size_t)b * 34 + ytile * 4) * 32 * CDIM;
        #pragma unroll
        for (int i = 0; i < 12; i++) {
            int f = tid + i * 256;
            int k16 = f & 15, x = (f >> 4) & 31, rr = f >> 9;
            CP_ASYNC16(sbase + ((rr * 34 + x + 1) * CBH + k16 * 8) * 2,
                       bsrc + (rr * 32 + x) * CDIM + k16 * 8);
        }
        CP_COMMIT();
    }

    const __half* wbase = w_h + (size_t)b * 9 * CDIM * CDIM;
    auto issueA = [&](int s) {
        const int tap = s >> 1, kc = s & 1;
        const uint32_t sa = sbase + (B_RES + (s % 3) * A_STG) * 2;
        const __half* wsrc = wbase + tap * (CDIM * CDIM) + kc * 64;
        #pragma unroll
        for (int i = 0; i < 4; i++) {
            int f = tid + i * 256;
            int r = f >> 3, k16 = f & 7;
            CP_ASYNC16(sa + (r * SH + k16 * 8) * 2, wsrc + r * CDIM + k16 * 8);
        }
        CP_COMMIT();
    };

    const int aRow = ((lane >> 3) & 1) * 8 + (lane & 7);
    const int aK   = (lane >> 4) * 8;
    const int m    = lane >> 3;
    const int bRow = (m >> 1) * 8 + (lane & 7);
    const int bK   = (m & 1) * 8;
    int rrB[2], xB[2];
    #pragma unroll
    for (int ntp = 0; ntp < 2; ntp++) {
        int px = pwv * 32 + ntp * 16 + bRow;
        rrB[ntp] = px >> 5;
        xB[ntp]  = px & 31;
    }

    float acc[4][4][4];
    #pragma unroll
    for (int mt = 0; mt < 4; mt++)
        #pragma unroll
        for (int nt = 0; nt < 4; nt++)
            #pragma unroll
            for (int k = 0; k < 4; k++) acc[mt][nt][k] = 0.f;

    issueA(0); issueA(1);

    for (int s = 0; s < NSTG; s++) {
        if (s + 1 < NSTG) CP_WAIT(1);
        else              CP_WAIT(0);
        __syncthreads();
        if (s + 2 < NSTG) issueA(s + 2);

        const int tap = s >> 1, kc = s & 1;
        const int dy = tap / 3, dx = tap % 3;
        const uint32_t aBase = sbase + (B_RES + (s % 3) * A_STG) * 2;

        #pragma unroll
        for (int j = 0; j < 4; j++) {
            uint32_t af[4][4], bf[2][4];
            #pragma unroll
            for (int mt = 0; mt < 4; mt++) {
                uint32_t addr = aBase +
                    ((ow * 64 + mt * 16 + aRow) * SH + j * 16 + aK) * 2;
                LDSM_X4(af[mt][0], af[mt][1], af[mt][2], af[mt][3], addr);
            }
            #pragma unroll
            for (int ntp = 0; ntp < 2; ntp++) {
                uint32_t addr = sbase +
                    (((rrB[ntp] + dy) * 34 + xB[ntp] + dx) * CBH +
                     kc * 64 + j * 16 + bK) * 2;
                LDSM_X4(bf[ntp][0], bf[ntp][1], bf[ntp][2], bf[ntp][3], addr);
            }
            #pragma unroll
            for (int nt = 0; nt < 4; nt++) {
                uint32_t b0 = bf[nt >> 1][(nt & 1) * 2];
                uint32_t b1 = bf[nt >> 1][(nt & 1) * 2 + 1];
                #pragma unroll
                for (int mt = 0; mt < 4; mt++)
                    mma_f16(acc[mt][nt], af[mt], b0, b1);
            }
        }
    }

    // Epilogue: +per-sample bias, float2 stores
    const float* bsrc = qrep + (size_t)b * WDIM + WOFF;
    #pragma unroll
    for (int mt = 0; mt < 4; mt++) {
        int o  = ow * 64 + mt * 16 + g;
        float bl = __ldg(bsrc + o), bh = __ldg(bsrc + o + 8);
        #pragma unroll
        for (int nt = 0; nt < 4; nt++) {
            int px = ytile * 128 + pwv * 32 + nt * 8 + 2 * q;
            float2 v0 = make_float2(acc[mt][nt][0] + bl, acc[mt][nt][1] + bl);
            float2 v1 = make_float2(acc[mt][nt][2] + bh, acc[mt][nt][3] + bh);
            *reinterpret_cast<float2*>(out + ((size_t)b * CDIM + o)     * NPX + px) = v0;
            *reinterpret_cast<float2*>(out + ((size_t)b * CDIM + o + 8) * NPX + px) = v1;
        }
    }
}

// ===========================================================================
extern "C" void kernel_launch(void* const* d_in, const int* in_sizes, int n_in,
                              void* d_out, int out_size)
{
    const float* qrep = (const float*)d_in[0];   // (64, 147584)
    const float* lhs  = (const float*)d_in[1];   // (64, 128, 32, 32)
    const float* rhs  = (const float*)d_in[2];   // (64, 128, 32, 32)
    const float* pw   = (const float*)d_in[3];   // (128, 256)
    const float* pb   = (const float*)d_in[4];   // (128,)
    float* out = (float*)d_out;                  // (64, 128, 32, 32)

    static bool attr_done = false;
    if (!attr_done) {
        cudaFuncSetAttribute(prep_kernel,
            cudaFuncAttributeMaxDynamicSharedMemorySize, PREP_SMEM);
        cudaFuncSetAttribute(proj_kernel,
            cudaFuncAttributeMaxDynamicSharedMemorySize, PROJ_SMEM);
        cudaFuncSetAttribute(conv_kernel,
            cudaFuncAttributeMaxDynamicSharedMemorySize, CONV_SMEM);
        attr_done = true;
    }

    prep_kernel<<<1025, 256, PREP_SMEM>>>(qrep, lhs, rhs, pw);
    proj_kernel<<<dim3(8, BB), 256, PROJ_SMEM>>>(pb);
    conv_kernel<<<dim3(8, BB), 256, CONV_SMEM>>>(qrep, out);
}

// round 12
// speedup vs baseline: 1.1375x; 1.1375x over previous
#include <cuda_runtime.h>
#include <cuda_fp16.h>
#include <cstdint>

// Problem constants
#define BB    64
#define CDIM  128
#define NPX   1024
#define WDIM  147584          // 128*128*9 + 128
#define WOFF  147456

// ---------------------------------------------------------------------------
// Device scratch
// w_h   : fp16 conv weights            [b][tap=9][o=128][c=128]
// cat_k : fp16 concat input (layout-preserving) [b][c=256][px=1024]
// pw_h  : fp16 proj weights            [o=128][c=256]
// g_padh: fp16 projected input         [b][y=34][x=32][c=128]  (y pads = 0)
// ---------------------------------------------------------------------------
__device__ __half w_h  [(size_t)BB * 9 * CDIM * CDIM];
__device__ __half cat_k[(size_t)BB * 256 * NPX];
__device__ __half pw_h [CDIM * 256];
__device__ __half g_padh[(size_t)BB * 34 * 32 * CDIM];

// ===========================================================================
// helpers
// ===========================================================================
__device__ __forceinline__ uint32_t smem_u32(const void* p) {
    uint32_t a;
    asm("{ .reg .u64 t; cvta.to.shared.u64 t, %1; cvt.u32.u64 %0, t; }"
        : "=r"(a) : "l"(p));
    return a;
}

#define CP_ASYNC16(dst_u32, src_ptr) \
    asm volatile("cp.async.cg.shared.global [%0], [%1], 16;" \
                 :: "r"(dst_u32), "l"(src_ptr) : "memory")
#define CP_COMMIT() asm volatile("cp.async.commit_group;" ::: "memory")
#define CP_WAIT(N)  asm volatile("cp.async.wait_group %0;" :: "n"(N) : "memory")

#define LDSM_X4(r0,r1,r2,r3,addr) \
    asm volatile("ldmatrix.sync.aligned.m8n8.x4.shared.b16 {%0,%1,%2,%3}, [%4];" \
                 : "=r"(r0),"=r"(r1),"=r"(r2),"=r"(r3) : "r"(addr))
#define LDSM_X4T(r0,r1,r2,r3,addr) \
    asm volatile("ldmatrix.sync.aligned.m8n8.x4.trans.shared.b16 {%0,%1,%2,%3}, [%4];" \
                 : "=r"(r0),"=r"(r1),"=r"(r2),"=r"(r3) : "r"(addr))

// m16n8k16 fp16 MMA, fp32 accumulate
__device__ __forceinline__ void mma_f16(float* d, const uint32_t* a,
                                        uint32_t b0, uint32_t b1) {
    asm volatile(
        "mma.sync.aligned.m16n8k16.row.col.f32.f16.f16.f32 "
        "{%0,%1,%2,%3}, {%4,%5,%6,%7}, {%8,%9}, {%0,%1,%2,%3};"
        : "+f"(d[0]), "+f"(d[1]), "+f"(d[2]), "+f"(d[3])
        : "r"(a[0]), "r"(a[1]), "r"(a[2]), "r"(a[3]), "r"(b0), "r"(b1));
}

// ===========================================================================
// Kernel 0 (prep, 3 roles by block id):
//  blocks [0,512)    : wtrans  -> w_h            (smem staged)
//  blocks [512,1024) : cat fp32->fp16, SAME layout -> cat_k  (pure stream)
//  block  1024       : pw -> pw_h
// ===========================================================================
#define PREP_SMEM (16 * 1152 * 4)        // 73728 B (wtrans role)

__global__ __launch_bounds__(256) void prep_kernel(
    const float* __restrict__ qrep, const float* __restrict__ lhs,
    const float* __restrict__ rhs,  const float* __restrict__ pw)
{
    extern __shared__ float s[];
    const int blk = blockIdx.x, tid = threadIdx.x;

    if (blk < 512) {
        // ---- wtrans role: w_h[b][tap][o][c] = half(qrep[b, o*1152+c*9+tap])
        const int b = blk >> 3, obase = (blk & 7) * 16;
        const float* src = qrep + (size_t)b * WDIM + obase * 1152;
        #pragma unroll
        for (int i = 0; i < 18; i++) {
            int idx = tid + i * 256;
            *reinterpret_cast<float4*>(s + idx * 4) =
                *reinterpret_cast<const float4*>(src + idx * 4);
        }
        __syncthreads();
        #pragma unroll
        for (int i = 0; i < 18; i++) {
            int idx = tid + i * 256;
            int tap = idx >> 9, rem = idx & 511;
            int o = rem >> 5, c4 = rem & 31;
            const float* row = s + o * 1152 + tap;
            __half2 h0 = __floats2half2_rn(row[(c4*4+0)*9], row[(c4*4+1)*9]);
            __half2 h1 = __floats2half2_rn(row[(c4*4+2)*9], row[(c4*4+3)*9]);
            uint2 u;
            u.x = *reinterpret_cast<uint32_t*>(&h0);
            u.y = *reinterpret_cast<uint32_t*>(&h1);
            *reinterpret_cast<uint2*>(
                w_h + (((size_t)b * 9 + tap) * CDIM + obase + o) * CDIM + c4*4) = u;
        }
    } else if (blk < 1024) {
        // ---- cat role: cat_k[b][c][px] = half(cat[b][c][px]); layout kept,
        //      fully coalesced streaming conversion (no smem, no transpose).
        const size_t base4 = (size_t)(blk - 512) * (256 * 32);
        #pragma unroll
        for (int i = 0; i < 32; i++) {
            size_t f4 = base4 + tid + i * 256;
            size_t j  = f4 * 4;                 // flat float idx [b][c][px]
            int b  = (int)(j >> 18);
            int c  = (int)((j >> 10) & 255);
            int px = (int)(j & 1023);
            const float* src = (c < CDIM)
                ? (lhs + (((size_t)b * CDIM + c) << 10) + px)
                : (rhs + (((size_t)b * CDIM + (c - CDIM)) << 10) + px);
            float4 v = *reinterpret_cast<const float4*>(src);
            __half2 h0 = __floats2half2_rn(v.x, v.y);
            __half2 h1 = __floats2half2_rn(v.z, v.w);
            uint2 u;
            u.x = *reinterpret_cast<uint32_t*>(&h0);
            u.y = *reinterpret_cast<uint32_t*>(&h1);
            *reinterpret_cast<uint2*>(cat_k + j) = u;
        }
    } else {
        // ---- pw role: pw_h = half(pw), 32768 elements
        #pragma unroll
        for (int i = 0; i < 32; i++) {
            int f = (tid + i * 256) * 4;
            float4 v = *reinterpret_cast<const float4*>(pw + f);
            __half2 h0 = __floats2half2_rn(v.x, v.y);
            __half2 h1 = __floats2half2_rn(v.z, v.w);
            uint2 u;
            u.x = *reinterpret_cast<uint32_t*>(&h0);
            u.y = *reinterpret_cast<uint32_t*>(&h1);
            *reinterpret_cast<uint2*>(pw_h + f) = u;
        }
    }
}

// ===========================================================================
// Kernel 1: projection, fp16 m16n8k16.
// A = pw_h [o][c] rows, non-trans ldmatrix (stride 72).
// B = cat_k [c][px] tiles [64k][128px] (stride 136), TRANS ldmatrix:
//     [k][n] storage + .trans == row.col B fragment.
// CTA: 128 o x 128 px, 8 warps (2o x 4px). K=256: 4 stages, 3-ring, 1 sync.
// ===========================================================================
#define SH 72                                    // A smem row stride (halves)
#define PBSTH 136                                // proj B smem k-row stride
#define APH (128 * SH)                           // 9216 halves (A operand)
#define BPH (64 * PBSTH)                         // 8704 halves (B operand)
#define PSTGH (APH + BPH)                        // per-stage halves
#define PROJ_SMEM (3 * PSTGH * 2)                // 107520 B
#define PNST 4

__global__ __launch_bounds__(256, 2) void proj_kernel(const float* __restrict__ pb)
{
    extern __shared__ __half smh[];
    const int tid = threadIdx.x, lane = tid & 31, warp = tid >> 5;
    const int g = lane >> 2, q = lane & 3;
    const int ow = warp & 1, pwv = warp >> 1;
    const int b = blockIdx.y, pxbase = blockIdx.x * 128;
    const uint32_t sbase = smem_u32(smh);

    auto issue = [&](int s) {
        const uint32_t sa = sbase + ((s % 3) * PSTGH) * 2;
        const uint32_t sb = sa + APH * 2;
        #pragma unroll
        for (int i = 0; i < 4; i++) {            // A: 128 o x 64 k halves
            int f = tid + i * 256;
            int r = f >> 3, k16 = f & 7;
            CP_ASYNC16(sa + (r * SH + k16 * 8) * 2,
                       pw_h + r * 256 + s * 64 + k16 * 8);
        }
        #pragma unroll
        for (int i = 0; i < 4; i++) {            // B: 64 k x 128 px halves
            int f = tid + i * 256;
            int r = f >> 4, k16 = f & 15;        // r: k-row, k16: px 16B chunk
            CP_ASYNC16(sb + (r * PBSTH + k16 * 8) * 2,
                       cat_k + ((size_t)b * 256 + s * 64 + r) * NPX
                             + pxbase + k16 * 8);
        }
        CP_COMMIT();
    };

    const int aRow = ((lane >> 3) & 1) * 8 + (lane & 7);
    const int aK   = (lane >> 4) * 8;

    float acc[4][4][4];
    #pragma unroll
    for (int mt = 0; mt < 4; mt++)
        #pragma unroll
        for (int nt = 0; nt < 4; nt++)
            #pragma unroll
            for (int k = 0; k < 4; k++) acc[mt][nt][k] = 0.f;

    issue(0); issue(1);
    for (int s = 0; s < PNST; s++) {
        if (s + 1 < PNST) CP_WAIT(1);
        else              CP_WAIT(0);
        __syncthreads();
        if (s + 2 < PNST) issue(s + 2);

        const uint32_t aBase = sbase + ((s % 3) * PSTGH) * 2;
        const uint32_t bBase = aBase + APH * 2;
        #pragma unroll
        for (int j = 0; j < 4; j++) {
            uint32_t af[4][4], bf[2][4];
            #pragma unroll
            for (int mt = 0; mt < 4; mt++) {
                uint32_t addr = aBase +
                    ((ow * 64 + mt * 16 + aRow) * SH + j * 16 + aK) * 2;
                LDSM_X4(af[mt][0], af[mt][1], af[mt][2], af[mt][3], addr);
            }
            // B trans: storage row = k (j*16 + aRow), col = n (px within tile)
            #pragma unroll
            for (int ntp = 0; ntp < 2; ntp++) {
                uint32_t addr = bBase +
                    ((j * 16 + aRow) * PBSTH +
                     pwv * 32 + ntp * 16 + aK) * 2;
                LDSM_X4T(bf[ntp][0], bf[ntp][1], bf[ntp][2], bf[ntp][3], addr);
            }
            #pragma unroll
            for (int nt = 0; nt < 4; nt++) {
                uint32_t b0 = bf[nt >> 1][(nt & 1) * 2];
                uint32_t b1 = bf[nt >> 1][(nt & 1) * 2 + 1];
                #pragma unroll
                for (int mt = 0; mt < 4; mt++)
                    mma_f16(acc[mt][nt], af[mt], b0, b1);
            }
        }
    }
    __syncthreads();                             // smem reused as T below

    // Epilogue: +bias, transpose through smem, fp16 store to g_padh
    float* T = reinterpret_cast<float*>(smh);    // [128 px][132]
    #pragma unroll
    for (int mt = 0; mt < 4; mt++) {
        int o = ow * 64 + mt * 16 + g;
        float bl = __ldg(pb + o), bh = __ldg(pb + o + 8);
        #pragma unroll
        for (int nt = 0; nt < 4; nt++) {
            int n0 = pwv * 32 + nt * 8 + 2 * q;
            T[n0 * 132 + o]           = acc[mt][nt][0] + bl;
            T[(n0 + 1) * 132 + o]     = acc[mt][nt][1] + bl;
            T[n0 * 132 + o + 8]       = acc[mt][nt][2] + bh;
            T[(n0 + 1) * 132 + o + 8] = acc[mt][nt][3] + bh;
        }
    }
    __syncthreads();
    #pragma unroll
    for (int i = 0; i < 16; i++) {
        int idx = tid + i * 256;
        int row = idx >> 5, c4 = idx & 31;
        int px = pxbase + row, y = px >> 5, x = px & 31;
        float4 v = *reinterpret_cast<const float4*>(T + row * 132 + c4 * 4);
        __half2 h0 = __floats2half2_rn(v.x, v.y);
        __half2 h1 = __floats2half2_rn(v.z, v.w);
        uint2 u;
        u.x = *reinterpret_cast<uint32_t*>(&h0);
        u.y = *reinterpret_cast<uint32_t*>(&h1);
        *reinterpret_cast<uint2*>(
            g_padh + (((size_t)b * 34 + 1 + y) * 32 + x) * CDIM + c4 * 4) = u;
    }
}

// ===========================================================================
// Kernel 2: conv, fp16 m16n8k16, RESIDENT B window + streamed A. (R10 proven)
// ===========================================================================
#define CBH 136                                  // B smem (row,x) stride (halves)
#define B_RES (6 * 34 * CBH)                     // 27744 halves
#define A_STG (128 * SH)                         // 9216 halves
#define CONV_SMEM ((B_RES + 3 * A_STG) * 2)      // 110784 B
#define NSTG 18

__global__ __launch_bounds__(256, 2) void conv_kernel(
    const float* __restrict__ qrep, float* __restrict__ out)
{
    extern __shared__ __half smh[];
    const int tid = threadIdx.x, lane = tid & 31, warp = tid >> 5;
    const int g = lane >> 2, q = lane & 3;
    const int ow = warp & 1, pwv = warp >> 1;
    const int ytile = blockIdx.x, b = blockIdx.y;
    const uint32_t sbase = smem_u32(smh);

    // ---- B: zero the two x-pad column slots, then load the 6x32 window
    #pragma unroll
    for (int i = tid; i < 6 * 2 * 16; i += 256) {
        int rr = i >> 5, rem = i & 31;
        int side = rem >> 4, u = rem & 15;
        int x = side ? 33 : 0;
        *reinterpret_cast<uint4*>(smh + (rr * 34 + x) * CBH + u * 8) =
            make_uint4(0, 0, 0, 0);
    }
    {
        const __half* bsrc = g_padh + ((size_t)b * 34 + ytile * 4) * 32 * CDIM;
        #pragma unroll
        for (int i = 0; i < 12; i++) {
            int f = tid + i * 256;
            int k16 = f & 15, x = (f >> 4) & 31, rr = f >> 9;
            CP_ASYNC16(sbase + ((rr * 34 + x + 1) * CBH + k16 * 8) * 2,
                       bsrc + (rr * 32 + x) * CDIM + k16 * 8);
        }
        CP_COMMIT();
    }

    const __half* wbase = w_h + (size_t)b * 9 * CDIM * CDIM;
    auto issueA = [&](int s) {
        const int tap = s >> 1, kc = s & 1;
        const uint32_t sa = sbase + (B_RES + (s % 3) * A_STG) * 2;
        const __half* wsrc = wbase + tap * (CDIM * CDIM) + kc * 64;
        #pragma unroll
        for (int i = 0; i < 4; i++) {
            int f = tid + i * 256;
            int r = f >> 3, k16 = f & 7;
            CP_ASYNC16(sa + (r * SH + k16 * 8) * 2, wsrc + r * CDIM + k16 * 8);
        }
        CP_COMMIT();
    };

    const int aRow = ((lane >> 3) & 1) * 8 + (lane & 7);
    const int aK   = (lane >> 4) * 8;
    const int m    = lane >> 3;
    const int bRow = (m >> 1) * 8 + (lane & 7);
    const int bK   = (m & 1) * 8;
    int rrB[2], xB[2];
    #pragma unroll
    for (int ntp = 0; ntp < 2; ntp++) {
        int px = pwv * 32 + ntp * 16 + bRow;
        rrB[ntp] = px >> 5;
        xB[ntp]  = px & 31;
    }

    float acc[4][4][4];
    #pragma unroll
    for (int mt = 0; mt < 4; mt++)
        #pragma unroll
        for (int nt = 0; nt < 4; nt++)
            #pragma unroll
            for (int k = 0; k < 4; k++) acc[mt][nt][k] = 0.f;

    issueA(0); issueA(1);

    for (int s = 0; s < NSTG; s++) {
        if (s + 1 < NSTG) CP_WAIT(1);
        else              CP_WAIT(0);
        __syncthreads();
        if (s + 2 < NSTG) issueA(s + 2);

        const int tap = s >> 1, kc = s & 1;
        const int dy = tap / 3, dx = tap % 3;
        const uint32_t aBase = sbase + (B_RES + (s % 3) * A_STG) * 2;

        #pragma unroll
        for (int j = 0; j < 4; j++) {
            uint32_t af[4][4], bf[2][4];
            #pragma unroll
            for (int mt = 0; mt < 4; mt++) {
                uint32_t addr = aBase +
                    ((ow * 64 + mt * 16 + aRow) * SH + j * 16 + aK) * 2;
                LDSM_X4(af[mt][0], af[mt][1], af[mt][2], af[mt][3], addr);
            }
            #pragma unroll
            for (int ntp = 0; ntp < 2; ntp++) {
                uint32_t addr = sbase +
                    (((rrB[ntp] + dy) * 34 + xB[ntp] + dx) * CBH +
                     kc * 64 + j * 16 + bK) * 2;
                LDSM_X4(bf[ntp][0], bf[ntp][1], bf[ntp][2], bf[ntp][3], addr);
            }
            #pragma unroll
            for (int nt = 0; nt < 4; nt++) {
                uint32_t b0 = bf[nt >> 1][(nt & 1) * 2];
                uint32_t b1 = bf[nt >> 1][(nt & 1) * 2 + 1];
                #pragma unroll
                for (int mt = 0; mt < 4; mt++)
                    mma_f16(acc[mt][nt], af[mt], b0, b1);
            }
        }
    }

    // Epilogue: +per-sample bias, float2 stores
    const float* bsrc = qrep + (size_t)b * WDIM + WOFF;
    #pragma unroll
    for (int mt = 0; mt < 4; mt++) {
        int o  = ow * 64 + mt * 16 + g;
        float bl = __ldg(bsrc + o), bh = __ldg(bsrc + o + 8);
        #pragma unroll
        for (int nt = 0; nt < 4; nt++) {
            int px = ytile * 128 + pwv * 32 + nt * 8 + 2 * q;
            float2 v0 = make_float2(acc[mt][nt][0] + bl, acc[mt][nt][1] + bl);
            float2 v1 = make_float2(acc[mt][nt][2] + bh, acc[mt][nt][3] + bh);
            *reinterpret_cast<float2*>(out + ((size_t)b * CDIM + o)     * NPX + px) = v0;
            *reinterpret_cast<float2*>(out + ((size_t)b * CDIM + o + 8) * NPX + px) = v1;
        }
    }
}

// ===========================================================================
extern "C" void kernel_launch(void* const* d_in, const int* in_sizes, int n_in,
                              void* d_out, int out_size)
{
    const float* qrep = (const float*)d_in[0];   // (64, 147584)
    const float* lhs  = (const float*)d_in[1];   // (64, 128, 32, 32)
    const float* rhs  = (const float*)d_in[2];   // (64, 128, 32, 32)
    const float* pw   = (const float*)d_in[3];   // (128, 256)
    const float* pb   = (const float*)d_in[4];   // (128,)
    float* out = (float*)d_out;                  // (64, 128, 32, 32)

    static bool attr_done = false;
    if (!attr_done) {
        cudaFuncSetAttribute(prep_kernel,
            cudaFuncAttributeMaxDynamicSharedMemorySize, PREP_SMEM);
        cudaFuncSetAttribute(proj_kernel,
            cudaFuncAttributeMaxDynamicSharedMemorySize, PROJ_SMEM);
        cudaFuncSetAttribute(conv_kernel,
            cudaFuncAttributeMaxDynamicSharedMemorySize, CONV_SMEM);
        attr_done = true;
    }

    prep_kernel<<<1025, 256, PREP_SMEM>>>(qrep, lhs, rhs, pw);
    proj_kernel<<<dim3(8, BB), 256, PROJ_SMEM>>>(pb);
    conv_kernel<<<dim3(8, BB), 256, CONV_SMEM>>>(qrep, out);
}

// round 13
// speedup vs baseline: 1.1410x; 1.0031x over previous
#include <cuda_runtime.h>
#include <cuda_fp16.h>
#include <cstdint>

// Problem constants
#define BB    64
#define CDIM  128
#define NPX   1024
#define WDIM  147584          // 128*128*9 + 128
#define WOFF  147456

// ---------------------------------------------------------------------------
// Device scratch
// w_h   : fp16 conv weights            [b][tap=9][o=128][c=128]
// cat_k : fp16 concat input (layout-preserving) [b][c=256][px=1024]
// pw_h  : fp16 proj weights            [o=128][c=256]
// g_padh: fp16 projected input         [b][y=34][x=32][c=128]  (y pads = 0)
// ---------------------------------------------------------------------------
__device__ __half w_h  [(size_t)BB * 9 * CDIM * CDIM];
__device__ __half cat_k[(size_t)BB * 256 * NPX];
__device__ __half pw_h [CDIM * 256];
__device__ __half g_padh[(size_t)BB * 34 * 32 * CDIM];

// ===========================================================================
// helpers
// ===========================================================================
__device__ __forceinline__ uint32_t smem_u32(const void* p) {
    uint32_t a;
    asm("{ .reg .u64 t; cvta.to.shared.u64 t, %1; cvt.u32.u64 %0, t; }"
        : "=r"(a) : "l"(p));
    return a;
}

#define CP_ASYNC16(dst_u32, src_ptr) \
    asm volatile("cp.async.cg.shared.global [%0], [%1], 16;" \
                 :: "r"(dst_u32), "l"(src_ptr) : "memory")
#define CP_COMMIT() asm volatile("cp.async.commit_group;" ::: "memory")
#define CP_WAIT(N)  asm volatile("cp.async.wait_group %0;" :: "n"(N) : "memory")

#define LDSM_X4(r0,r1,r2,r3,addr) \
    asm volatile("ldmatrix.sync.aligned.m8n8.x4.shared.b16 {%0,%1,%2,%3}, [%4];" \
                 : "=r"(r0),"=r"(r1),"=r"(r2),"=r"(r3) : "r"(addr))
#define LDSM_X4T(r0,r1,r2,r3,addr) \
    asm volatile("ldmatrix.sync.aligned.m8n8.x4.trans.shared.b16 {%0,%1,%2,%3}, [%4];" \
                 : "=r"(r0),"=r"(r1),"=r"(r2),"=r"(r3) : "r"(addr))

// m16n8k16 fp16 MMA, fp32 accumulate
__device__ __forceinline__ void mma_f16(float* d, const uint32_t* a,
                                        uint32_t b0, uint32_t b1) {
    asm volatile(
        "mma.sync.aligned.m16n8k16.row.col.f32.f16.f16.f32 "
        "{%0,%1,%2,%3}, {%4,%5,%6,%7}, {%8,%9}, {%0,%1,%2,%3};"
        : "+f"(d[0]), "+f"(d[1]), "+f"(d[2]), "+f"(d[3])
        : "r"(a[0]), "r"(a[1]), "r"(a[2]), "r"(a[3]), "r"(b0), "r"(b1));
}

// ===========================================================================
// Kernel 0a (stream 2): wtrans only -> w_h (conv dependency, off proj path)
//   w_h[b][tap][o][c] = half(qrep[b, o*1152 + c*9 + tap])
// ===========================================================================
#define PREP_SMEM (16 * 1152 * 4)        // 73728 B

__global__ __launch_bounds__(256) void prep_w_kernel(const float* __restrict__ qrep)
{
    extern __shared__ float s[];
    const int blk = blockIdx.x, tid = threadIdx.x;
    const int b = blk >> 3, obase = (blk & 7) * 16;
    const float* src = qrep + (size_t)b * WDIM + obase * 1152;
    #pragma unroll
    for (int i = 0; i < 18; i++) {
        int idx = tid + i * 256;
        *reinterpret_cast<float4*>(s + idx * 4) =
            *reinterpret_cast<const float4*>(src + idx * 4);
    }
    __syncthreads();
    #pragma unroll
    for (int i = 0; i < 18; i++) {
        int idx = tid + i * 256;
        int tap = idx >> 9, rem = idx & 511;
        int o = rem >> 5, c4 = rem & 31;
        const float* row = s + o * 1152 + tap;
        __half2 h0 = __floats2half2_rn(row[(c4*4+0)*9], row[(c4*4+1)*9]);
        __half2 h1 = __floats2half2_rn(row[(c4*4+2)*9], row[(c4*4+3)*9]);
        uint2 u;
        u.x = *reinterpret_cast<uint32_t*>(&h0);
        u.y = *reinterpret_cast<uint32_t*>(&h1);
        *reinterpret_cast<uint2*>(
            w_h + (((size_t)b * 9 + tap) * CDIM + obase + o) * CDIM + c4*4) = u;
    }
}

// ===========================================================================
// Kernel 0b (default stream): cat fp32->fp16 stream + pw conversion
//  blocks [0,512): cat_k[b][c][px] = half(cat); block 512: pw_h
// ===========================================================================
__global__ __launch_bounds__(256) void prep_cat_kernel(
    const float* __restrict__ lhs, const float* __restrict__ rhs,
    const float* __restrict__ pw)
{
    const int blk = blockIdx.x, tid = threadIdx.x;
    if (blk < 512) {
        const size_t base4 = (size_t)blk * (256 * 32);
        #pragma unroll
        for (int i = 0; i < 32; i++) {
            size_t f4 = base4 + tid + i * 256;
            size_t j  = f4 * 4;                 // flat float idx [b][c][px]
            int b  = (int)(j >> 18);
            int c  = (int)((j >> 10) & 255);
            int px = (int)(j & 1023);
            const float* src = (c < CDIM)
                ? (lhs + (((size_t)b * CDIM + c) << 10) + px)
                : (rhs + (((size_t)b * CDIM + (c - CDIM)) << 10) + px);
            float4 v = *reinterpret_cast<const float4*>(src);
            __half2 h0 = __floats2half2_rn(v.x, v.y);
            __half2 h1 = __floats2half2_rn(v.z, v.w);
            uint2 u;
            u.x = *reinterpret_cast<uint32_t*>(&h0);
            u.y = *reinterpret_cast<uint32_t*>(&h1);
            *reinterpret_cast<uint2*>(cat_k + j) = u;
        }
    } else {
        #pragma unroll
        for (int i = 0; i < 32; i++) {
            int f = (tid + i * 256) * 4;
            float4 v = *reinterpret_cast<const float4*>(pw + f);
            __half2 h0 = __floats2half2_rn(v.x, v.y);
            __half2 h1 = __floats2half2_rn(v.z, v.w);
            uint2 u;
            u.x = *reinterpret_cast<uint32_t*>(&h0);
            u.y = *reinterpret_cast<uint32_t*>(&h1);
            *reinterpret_cast<uint2*>(pw_h + f) = u;
        }
    }
}

// ===========================================================================
// Kernel 1: projection, fp16 m16n8k16 (R12-proven).
// A = pw_h [o][c] non-trans ldmatrix; B = cat_k [k][px] tiles, TRANS ldmatrix.
// CTA: 128 o x 128 px, 8 warps. K=256: 4 stages, 3-ring, 1 sync.
// ===========================================================================
#define SH 72                                    // A smem row stride (halves)
#define PBSTH 136                                // proj B smem k-row stride
#define APH (128 * SH)                           // 9216 halves (A operand)
#define BPH (64 * PBSTH)                         // 8704 halves (B operand)
#define PSTGH (APH + BPH)                        // per-stage halves
#define PROJ_SMEM (3 * PSTGH * 2)                // 107520 B
#define PNST 4

__global__ __launch_bounds__(256, 2) void proj_kernel(const float* __restrict__ pb)
{
    extern __shared__ __half smh[];
    const int tid = threadIdx.x, lane = tid & 31, warp = tid >> 5;
    const int g = lane >> 2, q = lane & 3;
    const int ow = warp & 1, pwv = warp >> 1;
    const int b = blockIdx.y, pxbase = blockIdx.x * 128;
    const uint32_t sbase = smem_u32(smh);

    auto issue = [&](int s) {
        const uint32_t sa = sbase + ((s % 3) * PSTGH) * 2;
        const uint32_t sb = sa + APH * 2;
        #pragma unroll
        for (int i = 0; i < 4; i++) {            // A: 128 o x 64 k halves
            int f = tid + i * 256;
            int r = f >> 3, k16 = f & 7;
            CP_ASYNC16(sa + (r * SH + k16 * 8) * 2,
                       pw_h + r * 256 + s * 64 + k16 * 8);
        }
        #pragma unroll
        for (int i = 0; i < 4; i++) {            // B: 64 k x 128 px halves
            int f = tid + i * 256;
            int r = f >> 4, k16 = f & 15;
            CP_ASYNC16(sb + (r * PBSTH + k16 * 8) * 2,
                       cat_k + ((size_t)b * 256 + s * 64 + r) * NPX
                             + pxbase + k16 * 8);
        }
        CP_COMMIT();
    };

    const int aRow = ((lane >> 3) & 1) * 8 + (lane & 7);
    const int aK   = (lane >> 4) * 8;

    float acc[4][4][4];
    #pragma unroll
    for (int mt = 0; mt < 4; mt++)
        #pragma unroll
        for (int nt = 0; nt < 4; nt++)
            #pragma unroll
            for (int k = 0; k < 4; k++) acc[mt][nt][k] = 0.f;

    issue(0); issue(1);
    for (int s = 0; s < PNST; s++) {
        if (s + 1 < PNST) CP_WAIT(1);
        else              CP_WAIT(0);
        __syncthreads();
        if (s + 2 < PNST) issue(s + 2);

        const uint32_t aBase = sbase + ((s % 3) * PSTGH) * 2;
        const uint32_t bBase = aBase + APH * 2;
        #pragma unroll
        for (int j = 0; j < 4; j++) {
            uint32_t af[4][4], bf[2][4];
            #pragma unroll
            for (int mt = 0; mt < 4; mt++) {
                uint32_t addr = aBase +
                    ((ow * 64 + mt * 16 + aRow) * SH + j * 16 + aK) * 2;
                LDSM_X4(af[mt][0], af[mt][1], af[mt][2], af[mt][3], addr);
            }
            #pragma unroll
            for (int ntp = 0; ntp < 2; ntp++) {
                uint32_t addr = bBase +
                    ((j * 16 + aRow) * PBSTH +
                     pwv * 32 + ntp * 16 + aK) * 2;
                LDSM_X4T(bf[ntp][0], bf[ntp][1], bf[ntp][2], bf[ntp][3], addr);
            }
            #pragma unroll
            for (int nt = 0; nt < 4; nt++) {
                uint32_t b0 = bf[nt >> 1][(nt & 1) * 2];
                uint32_t b1 = bf[nt >> 1][(nt & 1) * 2 + 1];
                #pragma unroll
                for (int mt = 0; mt < 4; mt++)
                    mma_f16(acc[mt][nt], af[mt], b0, b1);
            }
        }
    }
    __syncthreads();                             // smem reused as T below

    // Epilogue: +bias, transpose through smem, fp16 store to g_padh
    float* T = reinterpret_cast<float*>(smh);    // [128 px][132]
    #pragma unroll
    for (int mt = 0; mt < 4; mt++) {
        int o = ow * 64 + mt * 16 + g;
        float bl = __ldg(pb + o), bh = __ldg(pb + o + 8);
        #pragma unroll
        for (int nt = 0; nt < 4; nt++) {
            int n0 = pwv * 32 + nt * 8 + 2 * q;
            T[n0 * 132 + o]           = acc[mt][nt][0] + bl;
            T[(n0 + 1) * 132 + o]     = acc[mt][nt][1] + bl;
            T[n0 * 132 + o + 8]       = acc[mt][nt][2] + bh;
            T[(n0 + 1) * 132 + o + 8] = acc[mt][nt][3] + bh;
        }
    }
    __syncthreads();
    #pragma unroll
    for (int i = 0; i < 16; i++) {
        int idx = tid + i * 256;
        int row = idx >> 5, c4 = idx & 31;
        int px = pxbase + row, y = px >> 5, x = px & 31;
        float4 v = *reinterpret_cast<const float4*>(T + row * 132 + c4 * 4);
        __half2 h0 = __floats2half2_rn(v.x, v.y);
        __half2 h1 = __floats2half2_rn(v.z, v.w);
        uint2 u;
        u.x = *reinterpret_cast<uint32_t*>(&h0);
        u.y = *reinterpret_cast<uint32_t*>(&h1);
        *reinterpret_cast<uint2*>(
            g_padh + (((size_t)b * 34 + 1 + y) * 32 + x) * CDIM + c4 * 4) = u;
    }
}

// ===========================================================================
// Kernel 2: conv, fp16 m16n8k16, RESIDENT B window + streamed A. (R10 proven)
// ===========================================================================
#define CBH 136                                  // B smem (row,x) stride (halves)
#define B_RES (6 * 34 * CBH)                     // 27744 halves
#define A_STG (128 * SH)                         // 9216 halves
#define CONV_SMEM ((B_RES + 3 * A_STG) * 2)      // 110784 B
#define NSTG 18

__global__ __launch_bounds__(256, 2) void conv_kernel(
    const float* __restrict__ qrep, float* __restrict__ out)
{
    extern __shared__ __half smh[];
    const int tid = threadIdx.x, lane = tid & 31, warp = tid >> 5;
    const int g = lane >> 2, q = lane & 3;
    const int ow = warp & 1, pwv = warp >> 1;
    const int ytile = blockIdx.x, b = blockIdx.y;
    const uint32_t sbase = smem_u32(smh);

    // ---- B: zero the two x-pad column slots, then load the 6x32 window
    #pragma unroll
    for (int i = tid; i < 6 * 2 * 16; i += 256) {
        int rr = i >> 5, rem = i & 31;
        int side = rem >> 4, u = rem & 15;
        int x = side ? 33 : 0;
        *reinterpret_cast<uint4*>(smh + (rr * 34 + x) * CBH + u * 8) =
            make_uint4(0, 0, 0, 0);
    }
    {
        const __half* bsrc = g_padh + ((size_t)b * 34 + ytile * 4) * 32 * CDIM;
        #pragma unroll
        for (int i = 0; i < 12; i++) {
            int f = tid + i * 256;
            int k16 = f & 15, x = (f >> 4) & 31, rr = f >> 9;
            CP_ASYNC16(sbase + ((rr * 34 + x + 1) * CBH + k16 * 8) * 2,
                       bsrc + (rr * 32 + x) * CDIM + k16 * 8);
        }
        CP_COMMIT();
    }

    const __half* wbase = w_h + (size_t)b * 9 * CDIM * CDIM;
    auto issueA = [&](int s) {
        const int tap = s >> 1, kc = s & 1;
        const uint32_t sa = sbase + (B_RES + (s % 3) * A_STG) * 2;
        const __half* wsrc = wbase + tap * (CDIM * CDIM) + kc * 64;
        #pragma unroll
        for (int i = 0; i < 4; i++) {
            int f = tid + i * 256;
            int r = f >> 3, k16 = f & 7;
            CP_ASYNC16(sa + (r * SH + k16 * 8) * 2, wsrc + r * CDIM + k16 * 8);
        }
        CP_COMMIT();
    };

    const int aRow = ((lane >> 3) & 1) * 8 + (lane & 7);
    const int aK   = (lane >> 4) * 8;
    const int m    = lane >> 3;
    const int bRow = (m >> 1) * 8 + (lane & 7);
    const int bK   = (m & 1) * 8;
    int rrB[2], xB[2];
    #pragma unroll
    for (int ntp = 0; ntp < 2; ntp++) {
        int px = pwv * 32 + ntp * 16 + bRow;
        rrB[ntp] = px >> 5;
        xB[ntp]  = px & 31;
    }

    float acc[4][4][4];
    #pragma unroll
    for (int mt = 0; mt < 4; mt++)
        #pragma unroll
        for (int nt = 0; nt < 4; nt++)
            #pragma unroll
            for (int k = 0; k < 4; k++) acc[mt][nt][k] = 0.f;

    issueA(0); issueA(1);

    for (int s = 0; s < NSTG; s++) {
        if (s + 1 < NSTG) CP_WAIT(1);
        else              CP_WAIT(0);
        __syncthreads();
        if (s + 2 < NSTG) issueA(s + 2);

        const int tap = s >> 1, kc = s & 1;
        const int dy = tap / 3, dx = tap % 3;
        const uint32_t aBase = sbase + (B_RES + (s % 3) * A_STG) * 2;

        #pragma unroll
        for (int j = 0; j < 4; j++) {
            uint32_t af[4][4], bf[2][4];
            #pragma unroll
            for (int mt = 0; mt < 4; mt++) {
                uint32_t addr = aBase +
                    ((ow * 64 + mt * 16 + aRow) * SH + j * 16 + aK) * 2;
                LDSM_X4(af[mt][0], af[mt][1], af[mt][2], af[mt][3], addr);
            }
            #pragma unroll
            for (int ntp = 0; ntp < 2; ntp++) {
                uint32_t addr = sbase +
                    (((rrB[ntp] + dy) * 34 + xB[ntp] + dx) * CBH +
                     kc * 64 + j * 16 + bK) * 2;
                LDSM_X4(bf[ntp][0], bf[ntp][1], bf[ntp][2], bf[ntp][3], addr);
            }
            #pragma unroll
            for (int nt = 0; nt < 4; nt++) {
                uint32_t b0 = bf[nt >> 1][(nt & 1) * 2];
                uint32_t b1 = bf[nt >> 1][(nt & 1) * 2 + 1];
                #pragma unroll
                for (int mt = 0; mt < 4; mt++)
                    mma_f16(acc[mt][nt], af[mt], b0, b1);
            }
        }
    }

    // Epilogue: +per-sample bias, float2 stores
    const float* bsrc = qrep + (size_t)b * WDIM + WOFF;
    #pragma unroll
    for (int mt = 0; mt < 4; mt++) {
        int o  = ow * 64 + mt * 16 + g;
        float bl = __ldg(bsrc + o), bh = __ldg(bsrc + o + 8);
        #pragma unroll
        for (int nt = 0; nt < 4; nt++) {
            int px = ytile * 128 + pwv * 32 + nt * 8 + 2 * q;
            float2 v0 = make_float2(acc[mt][nt][0] + bl, acc[mt][nt][1] + bl);
            float2 v1 = make_float2(acc[mt][nt][2] + bh, acc[mt][nt][3] + bh);
            *reinterpret_cast<float2*>(out + ((size_t)b * CDIM + o)     * NPX + px) = v0;
            *reinterpret_cast<float2*>(out + ((size_t)b * CDIM + o + 8) * NPX + px) = v1;
        }
    }
}

// ===========================================================================
extern "C" void kernel_launch(void* const* d_in, const int* in_sizes, int n_in,
                              void* d_out, int out_size)
{
    const float* qrep = (const float*)d_in[0];   // (64, 147584)
    const float* lhs  = (const float*)d_in[1];   // (64, 128, 32, 32)
    const float* rhs  = (const float*)d_in[2];   // (64, 128, 32, 32)
    const float* pw   = (const float*)d_in[3];   // (128, 256)
    const float* pb   = (const float*)d_in[4];   // (128,)
    float* out = (float*)d_out;                  // (64, 128, 32, 32)

    static cudaStream_t s2 = nullptr;
    static cudaEvent_t evFork = nullptr, evJoin = nullptr;
    static bool init_done = false;
    if (!init_done) {
        cudaFuncSetAttribute(prep_w_kernel,
            cudaFuncAttributeMaxDynamicSharedMemorySize, PREP_SMEM);
        cudaFuncSetAttribute(proj_kernel,
            cudaFuncAttributeMaxDynamicSharedMemorySize, PROJ_SMEM);
        cudaFuncSetAttribute(conv_kernel,
            cudaFuncAttributeMaxDynamicSharedMemorySize, CONV_SMEM);
        cudaStreamCreateWithFlags(&s2, cudaStreamNonBlocking);
        cudaEventCreateWithFlags(&evFork, cudaEventDisableTiming);
        cudaEventCreateWithFlags(&evJoin, cudaEventDisableTiming);
        init_done = true;
    }

    // Fork: wtrans (conv-only dependency) runs on s2, overlapping cat+proj.
    cudaEventRecord(evFork, 0);
    cudaStreamWaitEvent(s2, evFork, 0);
    prep_w_kernel<<<512, 256, PREP_SMEM, s2>>>(qrep);

    prep_cat_kernel<<<513, 256>>>(lhs, rhs, pw);
    proj_kernel<<<dim3(8, BB), 256, PROJ_SMEM>>>(pb);

    // Join: conv needs both w_h (s2) and g_padh (default stream).
    cudaEventRecord(evJoin, s2);
    cudaStreamWaitEvent(0, evJoin, 0);
    conv_kernel<<<dim3(8, BB), 256, CONV_SMEM>>>(qrep, out);
}

// round 14
// speedup vs baseline: 1.2236x; 1.0723x over previous
#include <cuda_runtime.h>
#include <cuda_fp16.h>
#include <cstdint>

// Problem constants
#define BB    64
#define CDIM  128
#define NPX   1024
#define WDIM  147584          // 128*128*9 + 128
#define WOFF  147456

// ---------------------------------------------------------------------------
// Device scratch
// w_h   : fp16 conv weights            [b][tap=9][o=128][c=128]
// g_padh: fp16 projected input         [b][y=34][x=32][c=128]  (y pads = 0)
// ---------------------------------------------------------------------------
__device__ __half w_h   [(size_t)BB * 9 * CDIM * CDIM];
__device__ __half g_padh[(size_t)BB * 34 * 32 * CDIM];

// ===========================================================================
// helpers
// ===========================================================================
__device__ __forceinline__ uint32_t smem_u32(const void* p) {
    uint32_t a;
    asm("{ .reg .u64 t; cvta.to.shared.u64 t, %1; cvt.u32.u64 %0, t; }"
        : "=r"(a) : "l"(p));
    return a;
}

#define CP_ASYNC16(dst_u32, src_ptr) \
    asm volatile("cp.async.cg.shared.global [%0], [%1], 16;" \
                 :: "r"(dst_u32), "l"(src_ptr) : "memory")
#define CP_COMMIT() asm volatile("cp.async.commit_group;" ::: "memory")
#define CP_WAIT(N)  asm volatile("cp.async.wait_group %0;" :: "n"(N) : "memory")

#define LDSM_X4(r0,r1,r2,r3,addr) \
    asm volatile("ldmatrix.sync.aligned.m8n8.x4.shared.b16 {%0,%1,%2,%3}, [%4];" \
                 : "=r"(r0),"=r"(r1),"=r"(r2),"=r"(r3) : "r"(addr))
#define LDSM_X4T(r0,r1,r2,r3,addr) \
    asm volatile("ldmatrix.sync.aligned.m8n8.x4.trans.shared.b16 {%0,%1,%2,%3}, [%4];" \
                 : "=r"(r0),"=r"(r1),"=r"(r2),"=r"(r3) : "r"(addr))

// m16n8k16 fp16 MMA, fp32 accumulate
__device__ __forceinline__ void mma_f16(float* d, const uint32_t* a,
                                        uint32_t b0, uint32_t b1) {
    asm volatile(
        "mma.sync.aligned.m16n8k16.row.col.f32.f16.f16.f32 "
        "{%0,%1,%2,%3}, {%4,%5,%6,%7}, {%8,%9}, {%0,%1,%2,%3};"
        : "+f"(d[0]), "+f"(d[1]), "+f"(d[2]), "+f"(d[3])
        : "r"(a[0]), "r"(a[1]), "r"(a[2]), "r"(a[3]), "r"(b0), "r"(b1));
}

__device__ __forceinline__ uint2 f4_to_h4(float4 v) {
    __half2 h0 = __floats2half2_rn(v.x, v.y);
    __half2 h1 = __floats2half2_rn(v.z, v.w);
    uint2 u;
    u.x = *reinterpret_cast<uint32_t*>(&h0);
    u.y = *reinterpret_cast<uint32_t*>(&h1);
    return u;
}

// ===========================================================================
// Kernel 0 (stream 2): wtrans -> w_h (conv-only dependency)
//   w_h[b][tap][o][c] = half(qrep[b, o*1152 + c*9 + tap])
// ===========================================================================
#define PREP_SMEM (16 * 1152 * 4)        // 73728 B

__global__ __launch_bounds__(256) void prep_w_kernel(const float* __restrict__ qrep)
{
    extern __shared__ float s[];
    const int blk = blockIdx.x, tid = threadIdx.x;
    const int b = blk >> 3, obase = (blk & 7) * 16;
    const float* src = qrep + (size_t)b * WDIM + obase * 1152;
    #pragma unroll
    for (int i = 0; i < 18; i++) {
        int idx = tid + i * 256;
        *reinterpret_cast<float4*>(s + idx * 4) =
            *reinterpret_cast<const float4*>(src + idx * 4);
    }
    __syncthreads();
    #pragma unroll
    for (int i = 0; i < 18; i++) {
        int idx = tid + i * 256;
        int tap = idx >> 9, rem = idx & 511;
        int o = rem >> 5, c4 = rem & 31;
        const float* row = s + o * 1152 + tap;
        __half2 h0 = __floats2half2_rn(row[(c4*4+0)*9], row[(c4*4+1)*9]);
        __half2 h1 = __floats2half2_rn(row[(c4*4+2)*9], row[(c4*4+3)*9]);
        uint2 u;
        u.x = *reinterpret_cast<uint32_t*>(&h0);
        u.y = *reinterpret_cast<uint32_t*>(&h1);
        *reinterpret_cast<uint2*>(
            w_h + (((size_t)b * 9 + tap) * CDIM + obase + o) * CDIM + c4*4) = u;
    }
}

// ===========================================================================
// Kernel 1: projection, fp16 m16n8k16, INPUT-DIRECT.
// Reads pw/lhs/rhs fp32 via LDG, converts to fp16 in registers, STS into the
// exact smem layout R12's verified LDSM compute consumes.
// A = [o][c] stride 72 (non-trans LDSM); B = [k][px] stride 136 (trans LDSM).
// CTA: 128 o x 128 px, 8 warps (2o x 4px). K=256: 4 stages, 3-ring, 1 sync.
// ===========================================================================
#define SH 72                                    // A smem row stride (halves)
#define PBSTH 136                                // B smem k-row stride (halves)
#define APH (128 * SH)                           // 9216 halves (A operand)
#define BPH (64 * PBSTH)                         // 8704 halves (B operand)
#define PSTGH (APH + BPH)                        // 17920 halves per stage
#define PROJ_SMEM (3 * PSTGH * 2)                // 107520 B
#define PNST 4

__global__ __launch_bounds__(256, 2) void proj_kernel(
    const float* __restrict__ lhs, const float* __restrict__ rhs,
    const float* __restrict__ pw,  const float* __restrict__ pb)
{
    extern __shared__ __half smh[];
    const int tid = threadIdx.x, lane = tid & 31, warp = tid >> 5;
    const int g = lane >> 2, q = lane & 3;
    const int ow = warp & 1, pwv = warp >> 1;
    const int b = blockIdx.y, pxbase = blockIdx.x * 128;
    const uint32_t sbase = smem_u32(smh);

    auto fill = [&](int s) {
        __half* sa = smh + (s % 3) * PSTGH;
        __half* sb = sa + APH;
        // A: pw [128 o][64 c] fp32 -> fp16, stride 72
        #pragma unroll
        for (int i = 0; i < 8; i++) {
            int f = tid + i * 256;
            int r = f >> 4, c4 = f & 15;
            float4 v = *reinterpret_cast<const float4*>(pw + r * 256 + s * 64 + c4 * 4);
            *reinterpret_cast<uint2*>(sa + r * SH + c4 * 4) = f4_to_h4(v);
        }
        // B: cat [64 c][128 px] fp32 -> fp16, stride 136
        #pragma unroll
        for (int i = 0; i < 8; i++) {
            int f = tid + i * 256;
            int r = f >> 5, p4 = f & 31;
            int c = s * 64 + r;
            const float* src = (c < CDIM)
                ? (lhs + ((size_t)b * CDIM + c) * NPX + pxbase + p4 * 4)
                : (rhs + ((size_t)b * CDIM + (c - CDIM)) * NPX + pxbase + p4 * 4);
            float4 v = *reinterpret_cast<const float4*>(src);
            *reinterpret_cast<uint2*>(sb + r * PBSTH + p4 * 4) = f4_to_h4(v);
        }
    };

    const int aRow = ((lane >> 3) & 1) * 8 + (lane & 7);
    const int aK   = (lane >> 4) * 8;

    float acc[4][4][4];
    #pragma unroll
    for (int mt = 0; mt < 4; mt++)
        #pragma unroll
        for (int nt = 0; nt < 4; nt++)
            #pragma unroll
            for (int k = 0; k < 4; k++) acc[mt][nt][k] = 0.f;

    fill(0);
    for (int s = 0; s < PNST; s++) {
        __syncthreads();                          // fill(s) visible to all
        if (s + 1 < PNST) fill(s + 1);            // ring slot (s+1)%3 free

        const uint32_t aBase = sbase + ((s % 3) * PSTGH) * 2;
        const uint32_t bBase = aBase + APH * 2;
        #pragma unroll
        for (int j = 0; j < 4; j++) {
            uint32_t af[4][4], bf[2][4];
            #pragma unroll
            for (int mt = 0; mt < 4; mt++) {
                uint32_t addr = aBase +
                    ((ow * 64 + mt * 16 + aRow) * SH + j * 16 + aK) * 2;
                LDSM_X4(af[mt][0], af[mt][1], af[mt][2], af[mt][3], addr);
            }
            #pragma unroll
            for (int ntp = 0; ntp < 2; ntp++) {
                uint32_t addr = bBase +
                    ((j * 16 + aRow) * PBSTH + pwv * 32 + ntp * 16 + aK) * 2;
                LDSM_X4T(bf[ntp][0], bf[ntp][1], bf[ntp][2], bf[ntp][3], addr);
            }
            #pragma unroll
            for (int nt = 0; nt < 4; nt++) {
                uint32_t b0 = bf[nt >> 1][(nt & 1) * 2];
                uint32_t b1 = bf[nt >> 1][(nt & 1) * 2 + 1];
                #pragma unroll
                for (int mt = 0; mt < 4; mt++)
                    mma_f16(acc[mt][nt], af[mt], b0, b1);
            }
        }
    }
    __syncthreads();                             // smem reused as T below

    // Epilogue: +bias, transpose through smem, fp16 store to g_padh
    float* T = reinterpret_cast<float*>(smh);    // [128 px][132]
    #pragma unroll
    for (int mt = 0; mt < 4; mt++) {
        int o = ow * 64 + mt * 16 + g;
        float bl = __ldg(pb + o), bh = __ldg(pb + o + 8);
        #pragma unroll
        for (int nt = 0; nt < 4; nt++) {
            int n0 = pwv * 32 + nt * 8 + 2 * q;
            T[n0 * 132 + o]           = acc[mt][nt][0] + bl;
            T[(n0 + 1) * 132 + o]     = acc[mt][nt][1] + bl;
            T[n0 * 132 + o + 8]       = acc[mt][nt][2] + bh;
            T[(n0 + 1) * 132 + o + 8] = acc[mt][nt][3] + bh;
        }
    }
    __syncthreads();
    #pragma unroll
    for (int i = 0; i < 16; i++) {
        int idx = tid + i * 256;
        int row = idx >> 5, c4 = idx & 31;
        int px = pxbase + row, y = px >> 5, x = px & 31;
        float4 v = *reinterpret_cast<const float4*>(T + row * 132 + c4 * 4);
        *reinterpret_cast<uint2*>(
            g_padh + (((size_t)b * 34 + 1 + y) * 32 + x) * CDIM + c4 * 4) = f4_to_h4(v);
    }
}

// ===========================================================================
// Kernel 2: conv, fp16 m16n8k16, RESIDENT B window + streamed A. (R10 proven)
// ===========================================================================
#define CBH 136                                  // B smem (row,x) stride (halves)
#define B_RES (6 * 34 * CBH)                     // 27744 halves
#define A_STG (128 * SH)                         // 9216 halves
#define CONV_SMEM ((B_RES + 3 * A_STG) * 2)      // 110784 B
#define NSTG 18

__global__ __launch_bounds__(256, 2) void conv_kernel(
    const float* __restrict__ qrep, float* __restrict__ out)
{
    extern __shared__ __half smh[];
    const int tid = threadIdx.x, lane = tid & 31, warp = tid >> 5;
    const int g = lane >> 2, q = lane & 3;
    const int ow = warp & 1, pwv = warp >> 1;
    const int ytile = blockIdx.x, b = blockIdx.y;
    const uint32_t sbase = smem_u32(smh);

    // ---- B: zero the two x-pad column slots, then load the 6x32 window
    #pragma unroll
    for (int i = tid; i < 6 * 2 * 16; i += 256) {
        int rr = i >> 5, rem = i & 31;
        int side = rem >> 4, u = rem & 15;
        int x = side ? 33 : 0;
        *reinterpret_cast<uint4*>(smh + (rr * 34 + x) * CBH + u * 8) =
            make_uint4(0, 0, 0, 0);
    }
    {
        const __half* bsrc = g_padh + ((size_t)b * 34 + ytile * 4) * 32 * CDIM;
        #pragma unroll
        for (int i = 0; i < 12; i++) {
            int f = tid + i * 256;
            int k16 = f & 15, x = (f >> 4) & 31, rr = f >> 9;
            CP_ASYNC16(sbase + ((rr * 34 + x + 1) * CBH + k16 * 8) * 2,
                       bsrc + (rr * 32 + x) * CDIM + k16 * 8);
        }
        CP_COMMIT();
    }

    const __half* wbase = w_h + (size_t)b * 9 * CDIM * CDIM;
    auto issueA = [&](int s) {
        const int tap = s >> 1, kc = s & 1;
        const uint32_t sa = sbase + (B_RES + (s % 3) * A_STG) * 2;
        const __half* wsrc = wbase + tap * (CDIM * CDIM) + kc * 64;
        #pragma unroll
        for (int i = 0; i < 4; i++) {
            int f = tid + i * 256;
            int r = f >> 3, k16 = f & 7;
            CP_ASYNC16(sa + (r * SH + k16 * 8) * 2, wsrc + r * CDIM + k16 * 8);
        }
        CP_COMMIT();
    };

    const int aRow = ((lane >> 3) & 1) * 8 + (lane & 7);
    const int aK   = (lane >> 4) * 8;
    const int m    = lane >> 3;
    const int bRow = (m >> 1) * 8 + (lane & 7);
    const int bK   = (m & 1) * 8;
    int rrB[2], xB[2];
    #pragma unroll
    for (int ntp = 0; ntp < 2; ntp++) {
        int px = pwv * 32 + ntp * 16 + bRow;
        rrB[ntp] = px >> 5;
        xB[ntp]  = px & 31;
    }

    float acc[4][4][4];
    #pragma unroll
    for (int mt = 0; mt < 4; mt++)
        #pragma unroll
        for (int nt = 0; nt < 4; nt++)
            #pragma unroll
            for (int k = 0; k < 4; k++) acc[mt][nt][k] = 0.f;

    issueA(0); issueA(1);

    for (int s = 0; s < NSTG; s++) {
        if (s + 1 < NSTG) CP_WAIT(1);
        else              CP_WAIT(0);
        __syncthreads();
        if (s + 2 < NSTG) issueA(s + 2);

        const int tap = s >> 1, kc = s & 1;
        const int dy = tap / 3, dx = tap % 3;
        const uint32_t aBase = sbase + (B_RES + (s % 3) * A_STG) * 2;

        #pragma unroll
        for (int j = 0; j < 4; j++) {
            uint32_t af[4][4], bf[2][4];
            #pragma unroll
            for (int mt = 0; mt < 4; mt++) {
                uint32_t addr = aBase +
                    ((ow * 64 + mt * 16 + aRow) * SH + j * 16 + aK) * 2;
                LDSM_X4(af[mt][0], af[mt][1], af[mt][2], af[mt][3], addr);
            }
            #pragma unroll
            for (int ntp = 0; ntp < 2; ntp++) {
                uint32_t addr = sbase +
                    (((rrB[ntp] + dy) * 34 + xB[ntp] + dx) * CBH +
                     kc * 64 + j * 16 + bK) * 2;
                LDSM_X4(bf[ntp][0], bf[ntp][1], bf[ntp][2], bf[ntp][3], addr);
            }
            #pragma unroll
            for (int nt = 0; nt < 4; nt++) {
                uint32_t b0 = bf[nt >> 1][(nt & 1) * 2];
                uint32_t b1 = bf[nt >> 1][(nt & 1) * 2 + 1];
                #pragma unroll
                for (int mt = 0; mt < 4; mt++)
                    mma_f16(acc[mt][nt], af[mt], b0, b1);
            }
        }
    }

    // Epilogue: +per-sample bias, float2 stores
    const float* bsrc = qrep + (size_t)b * WDIM + WOFF;
    #pragma unroll
    for (int mt = 0; mt < 4; mt++) {
        int o  = ow * 64 + mt * 16 + g;
        float bl = __ldg(bsrc + o), bh = __ldg(bsrc + o + 8);
        #pragma unroll
        for (int nt = 0; nt < 4; nt++) {
            int px = ytile * 128 + pwv * 32 + nt * 8 + 2 * q;
            float2 v0 = make_float2(acc[mt][nt][0] + bl, acc[mt][nt][1] + bl);
            float2 v1 = make_float2(acc[mt][nt][2] + bh, acc[mt][nt][3] + bh);
            *reinterpret_cast<float2*>(out + ((size_t)b * CDIM + o)     * NPX + px) = v0;
            *reinterpret_cast<float2*>(out + ((size_t)b * CDIM + o + 8) * NPX + px) = v1;
        }
    }
}

// ===========================================================================
extern "C" void kernel_launch(void* const* d_in, const int* in_sizes, int n_in,
                              void* d_out, int out_size)
{
    const float* qrep = (const float*)d_in[0];   // (64, 147584)
    const float* lhs  = (const float*)d_in[1];   // (64, 128, 32, 32)
    const float* rhs  = (const float*)d_in[2];   // (64, 128, 32, 32)
    const float* pw   = (const float*)d_in[3];   // (128, 256)
    const float* pb   = (const float*)d_in[4];   // (128,)
    float* out = (float*)d_out;                  // (64, 128, 32, 32)

    static cudaStream_t s2 = nullptr;
    static cudaEvent_t evFork = nullptr, evJoin = nullptr;
    static bool init_done = false;
    if (!init_done) {
        cudaFuncSetAttribute(prep_w_kernel,
            cudaFuncAttributeMaxDynamicSharedMemorySize, PREP_SMEM);
        cudaFuncSetAttribute(proj_kernel,
            cudaFuncAttributeMaxDynamicSharedMemorySize, PROJ_SMEM);
        cudaFuncSetAttribute(conv_kernel,
            cudaFuncAttributeMaxDynamicSharedMemorySize, CONV_SMEM);
        cudaStreamCreateWithFlags(&s2, cudaStreamNonBlocking);
        cudaEventCreateWithFlags(&evFork, cudaEventDisableTiming);
        cudaEventCreateWithFlags(&evJoin, cudaEventDisableTiming);
        init_done = true;
    }

    // Fork: wtrans (conv-only dependency) on s2, fully parallel with proj
    // (proj now reads raw inputs directly and depends on nothing).
    cudaEventRecord(evFork, 0);
    cudaStreamWaitEvent(s2, evFork, 0);
    prep_w_kernel<<<512, 256, PREP_SMEM, s2>>>(qrep);

    proj_kernel<<<dim3(8, BB), 256, PROJ_SMEM>>>(lhs, rhs, pw, pb);

    // Join: conv needs w_h (s2) and g_padh (default stream).
    cudaEventRecord(evJoin, s2);
    cudaStreamWaitEvent(0, evJoin, 0);
    conv_kernel<<<dim3(8, BB), 256, CONV_SMEM>>>(qrep, out);
}